// round 1
// baseline (speedup 1.0000x reference)
#include <cuda_runtime.h>

// Problem constants (fixed by the reference).
#define NB 4096      // bodies
#define KB 16384     // broad-phase keep count
#define KE 4096      // exact-phase keep count
#define TPB 256      // threads per block
#define RPB 16       // rows per block (count/emit kernels)
#define JPT 16       // j-columns per thread (NB / TPB)
#define NBLK (NB / RPB)   // 256 blocks

// ---- device scratch (no allocations allowed) ----
__device__ int   g_cntA[NB];        // per-row AABB hit count
__device__ int   g_cntP[NB];        // per-row penetration count
__device__ int   g_allowedRow[NB];  // per-row # of A-hits under broad cutoff
__device__ int   g_prefE[NB];       // exclusive prefix of exact candidates per row
__device__ int   g_winner[NB];      // encoded (phase*KE + slot), -1 = untouched
__device__ float g_evx[KE];         // penetration vector x per exact slot
__device__ float g_evy[KE];         // penetration vector y per exact slot

// Pinned-rounding pair predicate — MUST be bit-identical across all kernels,
// because compaction ranks are computed independently in count/scan/emit.
__device__ __forceinline__ void pair_flags(float xi, float yi, float ri,
                                           float xj, float yj, float rj,
                                           bool self, bool& A, bool& P) {
    float dx = fabsf(__fsub_rn(xi, xj));
    float dy = fabsf(__fsub_rn(yi, yj));
    float rs = __fadd_rn(ri, rj);
    A = (dx <= rs) & (dy <= rs) & (!self);
    float d2 = __fadd_rn(__fmaf_rn(dy, dy, __fmul_rn(dx, dx)), 1e-12f);
    // pen_depth > 0  <=>  rs > sqrt(d2)  <=>  rs*rs > d2   (monotone equivalent)
    P = A & (d2 < __fmul_rn(rs, rs));
}

// Block-wide exclusive scan over 256 ints (warp shfl + 8-warp combine).
// Contains __syncthreads; must be called by all threads uniformly.
__device__ __forceinline__ int blk_excl_scan256(int v, int* sh8, int t) {
    int lane = t & 31, w = t >> 5;
    int x = v;
    #pragma unroll
    for (int d = 1; d < 32; d <<= 1) {
        int y = __shfl_up_sync(0xffffffffu, x, d);
        if (lane >= d) x += y;
    }
    if (lane == 31) sh8[w] = x;           // warp inclusive totals
    __syncthreads();
    if (t < 8) {
        int s = sh8[t];
        int acc = s;
        #pragma unroll
        for (int d = 1; d < 8; d <<= 1) {
            int y = __shfl_up_sync(0xffu, acc, d);
            if (t >= d) acc += y;
        }
        sh8[t] = acc - s;                 // exclusive warp base
    }
    __syncthreads();
    int r = sh8[w] + x - v;               // exclusive result
    __syncthreads();                      // protect sh8 for next call
    return r;
}

// ---------------- Kernel 1: per-row A / P counts (+ winner reset) -------------
__global__ void __launch_bounds__(TPB) k_count(const float* __restrict__ pos,
                                               const float* __restrict__ rad) {
    int t = threadIdx.x;
    int b = blockIdx.x;
    if (t < RPB) g_winner[b * RPB + t] = -1;

    // register-cache this thread's 16 bodies (columns)
    float jx[JPT], jy[JPT], jr[JPT];
    int j0 = t * JPT;
    const float2* p2 = (const float2*)pos;
    #pragma unroll
    for (int m = 0; m < JPT; m++) {
        float2 v = p2[j0 + m];
        jx[m] = v.x; jy[m] = v.y; jr[m] = rad[j0 + m];
    }

    __shared__ int sA, sP;
    if (t == 0) { sA = 0; sP = 0; }
    __syncthreads();

    int row0 = b * RPB;
    for (int r = 0; r < RPB; r++) {
        int i = row0 + r;
        float2 pi = p2[i];
        float ri = rad[i];
        unsigned mA = 0, mP = 0;
        #pragma unroll
        for (int m = 0; m < JPT; m++) {
            bool A, P;
            pair_flags(pi.x, pi.y, ri, jx[m], jy[m], jr[m], (j0 + m) == i, A, P);
            mA |= (unsigned)A << m;
            mP |= (unsigned)P << m;
        }
        int ca = __reduce_add_sync(0xffffffffu, __popc(mA));
        int cp = __reduce_add_sync(0xffffffffu, __popc(mP));
        if ((t & 31) == 0) { atomicAdd(&sA, ca); atomicAdd(&sP, cp); }
        __syncthreads();
        if (t == 0) { g_cntA[i] = sA; g_cntP[i] = sP; sA = 0; sP = 0; }
        __syncthreads();
    }
}

// ---------------- Kernel 2: global prefix sums, broad cutoff, exact prefix ----
__global__ void __launch_bounds__(TPB) k_scan(const float* __restrict__ pos,
                                              const float* __restrict__ rad) {
    __shared__ int sh8[8];
    __shared__ int shPartialRow;
    __shared__ int shPartialCand;
    int t = threadIdx.x;
    int r0 = t * JPT;

    int cA[JPT], cP[JPT];
    int sum = 0;
    #pragma unroll
    for (int m = 0; m < JPT; m++) {
        cA[m] = g_cntA[r0 + m];
        cP[m] = g_cntP[r0 + m];
        sum += cA[m];
    }
    if (t == 0) { shPartialRow = -1; shPartialCand = 0; }
    int base = blk_excl_scan256(sum, sh8, t);   // syncs inside

    // per-row allowed A-hits under the broad cutoff; detect the (unique) partial row
    int pref = base;
    #pragma unroll
    for (int m = 0; m < JPT; m++) {
        int i = r0 + m;
        int allowed = KB - pref;
        if (allowed < 0) allowed = 0;
        if (allowed > cA[m]) allowed = cA[m];
        g_allowedRow[i] = allowed;
        if (pref < KB && pref + cA[m] > KB) shPartialRow = i;
        pref += cA[m];
    }
    __syncthreads();

    int prow = shPartialRow;
    if (prow >= 0) {
        // rescan the partial row to count P-hits among its first `allowed` A-hits
        int allowed = g_allowedRow[prow];
        const float2* p2 = (const float2*)pos;
        float2 pi = p2[prow];
        float ri = rad[prow];
        unsigned mA = 0, mP = 0;
        int j0 = t * JPT;
        #pragma unroll
        for (int m = 0; m < JPT; m++) {
            int j = j0 + m;
            float2 pj = p2[j];
            bool A, P;
            pair_flags(pi.x, pi.y, ri, pj.x, pj.y, rad[j], j == prow, A, P);
            mA |= (unsigned)A << m;
            mP |= (unsigned)P << m;
        }
        int baseA = blk_excl_scan256(__popc(mA), sh8, t);
        int cnt = 0;
        #pragma unroll
        for (int m = 0; m < JPT; m++) {
            if ((mP >> m) & 1u) {
                int ar = baseA + __popc(mA & ((1u << m) - 1u));
                if (ar < allowed) cnt++;
            }
        }
        cnt = __reduce_add_sync(0xffffffffu, cnt);
        if ((t & 31) == 0) atomicAdd(&shPartialCand, cnt);
        __syncthreads();
    }
    int pc = (prow >= 0) ? shPartialCand : 0;

    // per-row exact-candidate counts -> exclusive prefix g_prefE
    int cC[JPT];
    int sumC = 0;
    pref = base;
    #pragma unroll
    for (int m = 0; m < JPT; m++) {
        int c;
        if (pref + cA[m] <= KB)      c = cP[m];   // row fully under broad cutoff
        else if (pref >= KB)         c = 0;       // row fully beyond cutoff
        else                         c = pc;      // the partial row
        cC[m] = c;
        sumC += c;
        pref += cA[m];
    }
    int baseC = blk_excl_scan256(sumC, sh8, t);
    #pragma unroll
    for (int m = 0; m < JPT; m++) {
        g_prefE[r0 + m] = baseC;
        baseC += cC[m];
    }
}

// ---------------- Kernel 3: emit exact candidates + priority writes -----------
__global__ void __launch_bounds__(TPB) k_emit(const float* __restrict__ pos,
                                              const float* __restrict__ rad) {
    __shared__ int sh8[8];
    int t = threadIdx.x;
    int b = blockIdx.x;

    float jx[JPT], jy[JPT], jr[JPT];
    int j0 = t * JPT;
    const float2* p2 = (const float2*)pos;
    #pragma unroll
    for (int m = 0; m < JPT; m++) {
        float2 v = p2[j0 + m];
        jx[m] = v.x; jy[m] = v.y; jr[m] = rad[j0 + m];
    }

    int row0 = b * RPB;
    for (int r = 0; r < RPB; r++) {
        int i = row0 + r;
        int baseE   = g_prefE[i];       // uniform across block
        int allowed = g_allowedRow[i];  // uniform across block
        if (baseE >= KE || allowed == 0) continue;   // uniform branch, sync-safe

        float2 pi = p2[i];
        float ri = rad[i];
        unsigned mA = 0, mP = 0;
        #pragma unroll
        for (int m = 0; m < JPT; m++) {
            bool A, P;
            pair_flags(pi.x, pi.y, ri, jx[m], jy[m], jr[m], (j0 + m) == i, A, P);
            mA |= (unsigned)A << m;
            mP |= (unsigned)P << m;
        }
        int baseA = blk_excl_scan256(__popc(mA), sh8, t);

        // candidate = penetration AND its within-row A-rank < allowed
        unsigned mC = 0;
        #pragma unroll
        for (int m = 0; m < JPT; m++) {
            if ((mP >> m) & 1u) {
                int ar = baseA + __popc(mA & ((1u << m) - 1u));
                if (ar < allowed) mC |= 1u << m;
            }
        }
        int slotBase = baseE + blk_excl_scan256(__popc(mC), sh8, t);

        unsigned mm = mC;
        while (mm) {
            int m = __ffs(mm) - 1;
            mm &= mm - 1;
            int slot = slotBase++;
            if (slot < KE) {
                int j = j0 + m;
                float dvx = __fsub_rn(pi.x, jx[m]);
                float dvy = __fsub_rn(pi.y, jy[m]);
                float rs  = __fadd_rn(ri, jr[m]);
                float d2  = __fadd_rn(__fmaf_rn(dvy, dvy, __fmul_rn(dvx, dvx)), 1e-12f);
                float dist = __fsqrt_rn(d2);
                float s = __fdiv_rn(__fsub_rn(rs, dist), dist);   // pen_depth / dist
                g_evx[slot] = __fmul_rn(dvx, s);
                g_evy[slot] = __fmul_rn(dvy, s);
                // i-phase priority = slot; j-phase priority = slot + KE (j after i)
                atomicMax(&g_winner[i], slot);
                atomicMax(&g_winner[j], slot + KE);
            }
        }
    }
}

// ---------------- Kernel 4: resolve (last-write-wins via priority) ------------
__global__ void k_resolve(const float* __restrict__ pos, float* __restrict__ out) {
    int bdy = blockIdx.x * blockDim.x + threadIdx.x;
    if (bdy >= NB) return;
    float x = pos[2 * bdy];
    float y = pos[2 * bdy + 1];
    int w = g_winner[bdy];
    if (w >= KE) {                 // a j-write wins: new_j = pos[b] - 0.5*ev
        int k = w - KE;
        x = __fsub_rn(x, __fmul_rn(0.5f, g_evx[k]));
        y = __fsub_rn(y, __fmul_rn(0.5f, g_evy[k]));
    } else if (w >= 0) {           // an i-write wins: new_i = pos[b] + 0.5*ev
        x = __fadd_rn(x, __fmul_rn(0.5f, g_evx[w]));
        y = __fadd_rn(y, __fmul_rn(0.5f, g_evy[w]));
    }
    out[2 * bdy]     = x;
    out[2 * bdy + 1] = y;
}

extern "C" void kernel_launch(void* const* d_in, const int* in_sizes, int n_in,
                              void* d_out, int out_size) {
    const float* pos;
    const float* rad;
    // metadata order: pos [N,2] then radius [N]; swap defensively by size.
    if (in_sizes[0] == 2 * NB) { pos = (const float*)d_in[0]; rad = (const float*)d_in[1]; }
    else                       { pos = (const float*)d_in[1]; rad = (const float*)d_in[0]; }
    float* out = (float*)d_out;

    k_count <<<NBLK, TPB>>>(pos, rad);
    k_scan  <<<1,    TPB>>>(pos, rad);
    k_emit  <<<NBLK, TPB>>>(pos, rad);
    k_resolve<<<(NB + 255) / 256, 256>>>(pos, out);
}